// round 14
// baseline (speedup 1.0000x reference)
#include <cuda_runtime.h>

#define Bb 4
#define Nn 1024
#define BN 4096
#define Ff 128
#define Rr 16
#define Ee 65536
#define NSTEPS 2

// ---------------- scratch (device globals; no runtime allocation) ----------------
__device__ float g_agg1[2][BN * Ff];           // psi1 neighbor aggregation (s, t)
__device__ float g_h[2][BN * Ff];              // h_s, h_t
__device__ float g_Shat[(size_t)Bb * Nn * Nn]; // 16 MB logits
__device__ float g_P[(size_t)Bb * Nn * Nn];    // 16 MB exp(Shat - m) cache
__device__ float g_invZ[BN];                   // 1/row sum-exp
__device__ float g_rt[BN * Rr];                // r_t
__device__ float g_aggR[BN * Rr];              // psi2 aggregation scratch
__device__ float g_As[NSTEPS][BN * Rr];        // A_s = o_s@Wm1 + bm1 per step
__device__ float g_Bt[BN * Rr];                // B_t = o_t@Wm1

__device__ __forceinline__ void red_add_f4(float* p, float4 v) {
    asm volatile("red.global.add.v4.f32 [%0], {%1,%2,%3,%4};"
                 :: "l"(p), "f"(v.x), "f"(v.y), "f"(v.z), "f"(v.w) : "memory");
}

__device__ __forceinline__ unsigned f2tf32(float x) {
    unsigned r;
    asm("cvt.rna.tf32.f32 %0, %1;" : "=r"(r) : "f"(x));
    return r;
}

__device__ __forceinline__ void mma_tf32(float* c, const unsigned* a, const unsigned* b) {
    asm volatile(
        "mma.sync.aligned.m16n8k8.row.col.f32.tf32.tf32.f32 "
        "{%0,%1,%2,%3}, {%4,%5,%6,%7}, {%8,%9}, {%0,%1,%2,%3};"
        : "+f"(c[0]), "+f"(c[1]), "+f"(c[2]), "+f"(c[3])
        : "r"(a[0]), "r"(a[1]), "r"(a[2]), "r"(a[3]), "r"(b[0]), "r"(b[1]));
}

// ---------------- zero kernels ----------------
__global__ void k_zero_agg1() {
    int i = blockIdx.x * blockDim.x + threadIdx.x;      // 262144 float4
    ((float4*)g_agg1)[i] = make_float4(0.f, 0.f, 0.f, 0.f);
}

__global__ void k_zeroRall() {                          // zero rt + aggR (32768 float4)
    int i = blockIdx.x * blockDim.x + threadIdx.x;
    if (i < 16384) ((float4*)g_rt)[i] = make_float4(0.f, 0.f, 0.f, 0.f);
    else ((float4*)g_aggR)[i - 16384] = make_float4(0.f, 0.f, 0.f, 0.f);
}

__global__ void k_zeroAggR() {                          // 16384 float4
    int i = blockIdx.x * blockDim.x + threadIdx.x;
    ((float4*)g_aggR)[i] = make_float4(0.f, 0.f, 0.f, 0.f);
}

// ---------------- psi1 aggregation: agg[dst] += x[src] (vector red) ----------------
__global__ void k_scatter128(const float* __restrict__ xs, const float* __restrict__ xt,
                             const int* __restrict__ eis, const int* __restrict__ eit) {
    int g = blockIdx.y;
    const float* x = g ? xt : xs;
    const int* ei = g ? eit : eis;
    float* agg = g_agg1[g];
    int idx = blockIdx.x * blockDim.x + threadIdx.x;    // < E*32
    int e = idx >> 5;
    int q = idx & 31;
    int src = ei[e];
    int dst = ei[Ee + e];
    float4 v = *(const float4*)&x[(size_t)src * Ff + 4 * q];
    red_add_f4(&agg[(size_t)dst * Ff + 4 * q], v);
}

// ---------------- psi1 GEMM: h = relu(x@Ws + agg@Wn + b1) ----------------
// BM=64, BN=64, K=256 (x||agg phases); 256 threads; 4x4 micro; double-buffered
__global__ __launch_bounds__(256) void k_psi1(
    const float* __restrict__ xs, const float* __restrict__ xt,
    const float* __restrict__ Ws, const float* __restrict__ Wn,
    const float* __restrict__ bias) {
    __shared__ float sA[2][16][68];
    __shared__ float sW[2][16][68];

    int g = blockIdx.z;
    int c0 = blockIdx.y * 64;
    int row0 = blockIdx.x * 64;
    const float* x = g ? xt : xs;
    const float* agg = g_agg1[g];
    float* h = g_h[g];

    int tid = threadIdx.x;
    int tx = tid & 15, ty = tid >> 4;
    int ar_ = tid & 63, ak = (tid >> 6) * 4;
    int wr = tid >> 4, wc = 4 * (tid & 15);

    float acc[4][4];
#pragma unroll
    for (int i = 0; i < 4; ++i)
#pragma unroll
        for (int j = 0; j < 4; ++j) acc[i][j] = 0.f;

#define LOAD_A(c) (*(const float4*)&(((c) < 8) ? x : agg)[(size_t)(row0 + ar_) * Ff + (((c)*16) & 127) + ak])
#define LOAD_W(c) (*(const float4*)&(((c) < 8) ? Ws : Wn)[(size_t)((((c)*16) & 127) + wr) * Ff + c0 + wc])

    float4 va = LOAD_A(0);
    float4 vw = LOAD_W(0);
    sA[0][ak + 0][ar_] = va.x; sA[0][ak + 1][ar_] = va.y;
    sA[0][ak + 2][ar_] = va.z; sA[0][ak + 3][ar_] = va.w;
    *(float4*)&sW[0][wr][wc] = vw;
    va = LOAD_A(1);
    vw = LOAD_W(1);
    __syncthreads();

    for (int c = 0; c < 16; ++c) {
        int cur = c & 1;
        if (c < 15) {
            int nxt = cur ^ 1;
            sA[nxt][ak + 0][ar_] = va.x; sA[nxt][ak + 1][ar_] = va.y;
            sA[nxt][ak + 2][ar_] = va.z; sA[nxt][ak + 3][ar_] = va.w;
            *(float4*)&sW[nxt][wr][wc] = vw;
        }
        if (c < 14) {
            va = LOAD_A(c + 2);
            vw = LOAD_W(c + 2);
        }
#pragma unroll
        for (int k = 0; k < 16; ++k) {
            float4 a = *(float4*)&sA[cur][k][4 * ty];
            float4 w = *(float4*)&sW[cur][k][4 * tx];
            float arr[4] = {a.x, a.y, a.z, a.w};
#pragma unroll
            for (int i = 0; i < 4; ++i) {
                acc[i][0] += arr[i] * w.x; acc[i][1] += arr[i] * w.y;
                acc[i][2] += arr[i] * w.z; acc[i][3] += arr[i] * w.w;
            }
        }
        __syncthreads();
    }
#undef LOAD_A
#undef LOAD_W

    float4 bv = *(const float4*)&bias[c0 + 4 * tx];
#pragma unroll
    for (int i = 0; i < 4; ++i) {
        int row = row0 + 4 * ty + i;
        float4 o;
        o.x = fmaxf(acc[i][0] + bv.x, 0.f);
        o.y = fmaxf(acc[i][1] + bv.y, 0.f);
        o.z = fmaxf(acc[i][2] + bv.z, 0.f);
        o.w = fmaxf(acc[i][3] + bv.w, 0.f);
        *(float4*)&h[(size_t)row * Ff + c0 + 4 * tx] = o;
    }
}

// ---------------- S_hat = h_s @ h_t^T per batch (3xTF32 tensor-core) ----------------
// 128x128 tile, 8 warps (2x4), warp tile 64x32; m16n8k8 atoms; BK=16, 8 chunks
__global__ __launch_bounds__(256, 2) void k_shat() {
    __shared__ float sAb[128][20];   // A hi (tf32-rounded)
    __shared__ float sAl[128][20];   // A lo
    __shared__ float sBb[128][20];   // B hi
    __shared__ float sBl[128][20];   // B lo

    int b = blockIdx.z;
    int t0 = blockIdx.x * 128;
    int s0 = blockIdx.y * 128;
    const float* hs = g_h[0] + (size_t)b * Nn * Ff;
    const float* ht = g_h[1] + (size_t)b * Nn * Ff;

    int tid = threadIdx.x;
    int lane = tid & 31;
    int w = tid >> 5;
    int wm = w >> 2;          // 0..1 : s-offset 64*wm
    int wn = w & 3;           // 0..3 : t-offset 32*wn
    int qr = lane >> 2;       // 0..7
    int qc = lane & 3;        // 0..3

    int lrow = tid >> 1;      // 0..127
    int lcol = (tid & 1) * 8; // 0 or 8

    const float* pa = &hs[(size_t)(s0 + lrow) * Ff + lcol];
    const float* pb = &ht[(size_t)(t0 + lrow) * Ff + lcol];

    float acc[4][4][4];       // [ma][na][reg]
#pragma unroll
    for (int i = 0; i < 4; ++i)
#pragma unroll
        for (int j = 0; j < 4; ++j)
#pragma unroll
            for (int r = 0; r < 4; ++r) acc[i][j][r] = 0.f;

    // preload chunk 0
    float4 ga0 = *(const float4*)pa;
    float4 ga1 = *(const float4*)(pa + 4);
    float4 gb0 = *(const float4*)pb;
    float4 gb1 = *(const float4*)(pb + 4);

    for (int c = 0; c < 8; ++c) {
        __syncthreads();
        {
            float av[8] = {ga0.x, ga0.y, ga0.z, ga0.w, ga1.x, ga1.y, ga1.z, ga1.w};
            float bv[8] = {gb0.x, gb0.y, gb0.z, gb0.w, gb1.x, gb1.y, gb1.z, gb1.w};
#pragma unroll
            for (int i = 0; i < 8; ++i) {
                unsigned hb = f2tf32(av[i]);
                float hf = __uint_as_float(hb);
                sAb[lrow][lcol + i] = hf;
                sAl[lrow][lcol + i] = __uint_as_float(f2tf32(av[i] - hf));
                unsigned hb2 = f2tf32(bv[i]);
                float hf2 = __uint_as_float(hb2);
                sBb[lrow][lcol + i] = hf2;
                sBl[lrow][lcol + i] = __uint_as_float(f2tf32(bv[i] - hf2));
            }
        }
        __syncthreads();

        if (c < 7) {
            const float* npa = pa + 16 * (c + 1);
            const float* npb = pb + 16 * (c + 1);
            ga0 = *(const float4*)npa;
            ga1 = *(const float4*)(npa + 4);
            gb0 = *(const float4*)npb;
            gb1 = *(const float4*)(npb + 4);
        }

#pragma unroll
        for (int s8 = 0; s8 < 2; ++s8) {
            int k0 = 8 * s8;
            unsigned Bbf[4][2], Blf[4][2];
#pragma unroll
            for (int na = 0; na < 4; ++na) {
                int trow = 32 * wn + 8 * na + qr;
                Bbf[na][0] = __float_as_uint(sBb[trow][k0 + qc]);
                Bbf[na][1] = __float_as_uint(sBb[trow][k0 + 4 + qc]);
                Blf[na][0] = __float_as_uint(sBl[trow][k0 + qc]);
                Blf[na][1] = __float_as_uint(sBl[trow][k0 + 4 + qc]);
            }
#pragma unroll
            for (int ma = 0; ma < 4; ++ma) {
                int ar0 = 64 * wm + 16 * ma + qr;
                unsigned Abf[4], Alf[4];
                Abf[0] = __float_as_uint(sAb[ar0][k0 + qc]);
                Abf[1] = __float_as_uint(sAb[ar0 + 8][k0 + qc]);
                Abf[2] = __float_as_uint(sAb[ar0][k0 + 4 + qc]);
                Abf[3] = __float_as_uint(sAb[ar0 + 8][k0 + 4 + qc]);
                Alf[0] = __float_as_uint(sAl[ar0][k0 + qc]);
                Alf[1] = __float_as_uint(sAl[ar0 + 8][k0 + qc]);
                Alf[2] = __float_as_uint(sAl[ar0][k0 + 4 + qc]);
                Alf[3] = __float_as_uint(sAl[ar0 + 8][k0 + 4 + qc]);
#pragma unroll
                for (int na = 0; na < 4; ++na) {
                    mma_tf32(acc[ma][na], Abf, Blf[na]);   // hi*lo
                    mma_tf32(acc[ma][na], Alf, Bbf[na]);   // lo*hi
                    mma_tf32(acc[ma][na], Abf, Bbf[na]);   // hi*hi
                }
            }
        }
    }

#pragma unroll
    for (int ma = 0; ma < 4; ++ma) {
#pragma unroll
        for (int na = 0; na < 4; ++na) {
            int row = s0 + 64 * wm + 16 * ma + qr;
            int col = t0 + 32 * wn + 8 * na + 2 * qc;
            float* d0 = &g_Shat[((size_t)(b * Nn + row)) * Nn + col];
            float* d1 = &g_Shat[((size_t)(b * Nn + row + 8)) * Nn + col];
            *(float2*)d0 = make_float2(acc[ma][na][0], acc[ma][na][1]);
            *(float2*)d1 = make_float2(acc[ma][na][2], acc[ma][na][3]);
        }
    }
}

// ---------------- initial stats: writes P, invZ, and S_0 in ONE pass ----------------
__global__ __launch_bounds__(256) void k_stats0(float* __restrict__ out) {
    int row = blockIdx.x;
    int tid = threadIdx.x;
    const float4* p = (const float4*)(g_Shat + (size_t)row * Nn);
    float4 v = p[tid];
    float m = fmaxf(fmaxf(v.x, v.y), fmaxf(v.z, v.w));
#pragma unroll
    for (int o = 16; o > 0; o >>= 1) m = fmaxf(m, __shfl_xor_sync(0xffffffffu, m, o));
    __shared__ float sred[8];
    __shared__ float sbc;
    int wid = tid >> 5, lane = tid & 31;
    if (lane == 0) sred[wid] = m;
    __syncthreads();
    if (tid == 0) {
        float mm = sred[0];
#pragma unroll
        for (int i = 1; i < 8; ++i) mm = fmaxf(mm, sred[i]);
        sbc = mm;
    }
    __syncthreads();
    m = sbc;
    float4 e;
    e.x = __expf(v.x - m);
    e.y = __expf(v.y - m);
    e.z = __expf(v.z - m);
    e.w = __expf(v.w - m);
    ((float4*)(g_P + (size_t)row * Nn))[tid] = e;
    float s = e.x + e.y + e.z + e.w;
#pragma unroll
    for (int o = 16; o > 0; o >>= 1) s += __shfl_xor_sync(0xffffffffu, s, o);
    if (lane == 0) sred[wid] = s;
    __syncthreads();
    if (tid == 0) {
        float ss = 0.f;
#pragma unroll
        for (int i = 0; i < 8; ++i) ss += sred[i];
        float iz = 1.0f / ss;
        sbc = iz;
        g_invZ[row] = iz;
    }
    __syncthreads();
    float iz = sbc;
    float4 o;
    o.x = e.x * iz; o.y = e.y * iz; o.z = e.z * iz; o.w = e.w * iz;
    ((float4*)(out + (size_t)row * Nn))[tid] = o;
}

// ---------------- r_t = softmax(S_hat)^T @ r_s  (uses cached P) ----------------
__global__ __launch_bounds__(128) void k_rt(const float* __restrict__ rs) {
    __shared__ float s_rs[128][Rr];
    __shared__ float s_iz[128];
    int b = blockIdx.z;
    int t0 = blockIdx.x * 128;
    int s0 = blockIdx.y * 128;
    int tid = threadIdx.x;
#pragma unroll
    for (int i = 0; i < 16; ++i) {
        int lin = tid + 128 * i;
        int r = lin >> 4, c = lin & 15;
        s_rs[r][c] = rs[((size_t)(b * Nn + s0 + r)) * Rr + c];
    }
    s_iz[tid] = g_invZ[b * Nn + s0 + tid];
    __syncthreads();

    int t = t0 + tid;
    float acc[Rr];
#pragma unroll
    for (int r = 0; r < Rr; ++r) acc[r] = 0.f;
    const float* sp = g_P + ((size_t)(b * Nn + s0)) * Nn + t;
#pragma unroll 4
    for (int s = 0; s < 128; ++s) {
        float w = sp[(size_t)s * Nn] * s_iz[s];
#pragma unroll
        for (int r = 0; r < Rr; ++r) acc[r] += w * s_rs[s][r];
    }
    float* rt = g_rt + (size_t)(b * Nn + t) * Rr;
#pragma unroll
    for (int q = 0; q < 4; ++q)
        red_add_f4(&rt[4 * q], make_float4(acc[4 * q], acc[4 * q + 1], acc[4 * q + 2], acc[4 * q + 3]));
}

// ---------------- psi2 aggregation (R=16, vector red) ----------------
__global__ void k_scatter16(int src_is_rt, const float* __restrict__ rext,
                            const int* __restrict__ ei) {
    int idx = blockIdx.x * blockDim.x + threadIdx.x;   // < E*4
    int e = idx >> 2;
    int q = idx & 3;
    const float* src = src_is_rt ? g_rt : rext;
    float4 v = *(const float4*)&src[(size_t)ei[e] * Rr + 4 * q];
    red_add_f4(&g_aggR[(size_t)ei[Ee + e] * Rr + 4 * q], v);
}

// ---------------- psi2 + Wm1 projection fused ----------------
__global__ __launch_bounds__(256) void k_psi2(
    int src_is_rt, const float* __restrict__ rext,
    const float* __restrict__ W2s, const float* __restrict__ W2n,
    const float* __restrict__ b2v, const float* __restrict__ Wm1,
    int use_bm1, const float* __restrict__ bm1v, int out_is_B, int step) {
    __shared__ float sr[16][17], sg[16][17], so[16][17];
    __shared__ float sWs[256], sWn[256], sWm[256];
    int tid = threadIdx.x;
    int r = tid >> 4, j = tid & 15;
    int row0 = blockIdx.x * 16;
    const float* src = src_is_rt ? g_rt : rext;
    sr[r][j] = src[(size_t)(row0 + r) * Rr + j];
    sg[r][j] = g_aggR[(size_t)(row0 + r) * Rr + j];
    sWs[tid] = W2s[tid];
    sWn[tid] = W2n[tid];
    sWm[tid] = Wm1[tid];
    __syncthreads();
    float acc = b2v[j];
#pragma unroll
    for (int k = 0; k < 16; ++k)
        acc += sr[r][k] * sWs[k * 16 + j] + sg[r][k] * sWn[k * 16 + j];
    so[r][j] = fmaxf(acc, 0.f);
    __syncthreads();
    float a2 = use_bm1 ? bm1v[j] : 0.f;
#pragma unroll
    for (int k = 0; k < 16; ++k) a2 += so[r][k] * sWm[k * 16 + j];
    float* dst = out_is_B ? g_Bt : g_As[step];
    dst[(size_t)(row0 + r) * Rr + j] = a2;
}

// ---------------- fused: S_hat += upd; row softmax stats; write P+invZ (mid) or S_L (final)
// block = 16 s-rows x full 1024 t; 256 threads; thread owns 4 t-cols per row.
// Bt traffic = 64KB/block * 256 blocks = 16MB (same as tiled k_upd; no amplification).
__global__ __launch_bounds__(256) void k_updstats2(int step, const float* __restrict__ Wm2,
                                                   const float* __restrict__ bm2v,
                                                   float* __restrict__ outF, int final_) {
    int b = blockIdx.y;
    int s0 = blockIdx.x * 16;
    int tid = threadIdx.x;
    int wid = tid >> 5, lane = tid & 31;

    __shared__ float sA[16][16];
    __shared__ float swm[16];
    __shared__ float sred[16][8];
    __shared__ float sbc[16];

    sA[tid >> 4][tid & 15] =
        g_As[step][(size_t)(b * Nn + s0 + (tid >> 4)) * Rr + (tid & 15)];
    if (tid < 16) swm[tid] = Wm2[tid];
    float bb = bm2v[0];
    __syncthreads();

    float acc[16][4];
#pragma unroll
    for (int j = 0; j < 4; ++j) {
        int t = 256 * j + tid;
        const float4* bp = (const float4*)&g_Bt[(size_t)(b * Nn + t) * Rr];
        float4 q0 = bp[0], q1 = bp[1], q2 = bp[2], q3 = bp[3];
        float Bk[16] = {q0.x, q0.y, q0.z, q0.w, q1.x, q1.y, q1.z, q1.w,
                        q2.x, q2.y, q2.z, q2.w, q3.x, q3.y, q3.z, q3.w};
#pragma unroll
        for (int s = 0; s < 16; ++s) {
            float u = bb;
#pragma unroll
            for (int k = 0; k < 16; ++k)
                u += fmaxf(sA[s][k] - Bk[k], 0.f) * swm[k];
            acc[s][j] = g_Shat[((size_t)(b * Nn + s0 + s)) * Nn + t] + u;
        }
    }

    if (!final_) {
#pragma unroll
        for (int s = 0; s < 16; ++s)
#pragma unroll
            for (int j = 0; j < 4; ++j)
                g_Shat[((size_t)(b * Nn + s0 + s)) * Nn + 256 * j + tid] = acc[s][j];
    }

    // row max (16 rows in parallel)
#pragma unroll
    for (int s = 0; s < 16; ++s) {
        float pm = fmaxf(fmaxf(acc[s][0], acc[s][1]), fmaxf(acc[s][2], acc[s][3]));
#pragma unroll
        for (int o = 16; o > 0; o >>= 1) pm = fmaxf(pm, __shfl_xor_sync(0xffffffffu, pm, o));
        if (lane == 0) sred[s][wid] = pm;
    }
    __syncthreads();
    if (tid < 16) {
        float mm = sred[tid][0];
#pragma unroll
        for (int w2 = 1; w2 < 8; ++w2) mm = fmaxf(mm, sred[tid][w2]);
        sbc[tid] = mm;
    }
    __syncthreads();

    // exp + row sum
#pragma unroll
    for (int s = 0; s < 16; ++s) {
        float m = sbc[s];
        acc[s][0] = __expf(acc[s][0] - m);
        acc[s][1] = __expf(acc[s][1] - m);
        acc[s][2] = __expf(acc[s][2] - m);
        acc[s][3] = __expf(acc[s][3] - m);
        float ps = acc[s][0] + acc[s][1] + acc[s][2] + acc[s][3];
#pragma unroll
        for (int o = 16; o > 0; o >>= 1) ps += __shfl_xor_sync(0xffffffffu, ps, o);
        if (lane == 0) sred[s][wid] = ps;
    }
    __syncthreads();
    if (tid < 16) {
        float ss = 0.f;
#pragma unroll
        for (int w2 = 0; w2 < 8; ++w2) ss += sred[tid][w2];
        float iz = 1.0f / ss;
        sbc[tid] = iz;
        if (!final_) g_invZ[b * Nn + s0 + tid] = iz;
    }
    __syncthreads();

    if (final_) {
#pragma unroll
        for (int s = 0; s < 16; ++s) {
            float iz = sbc[s];
#pragma unroll
            for (int j = 0; j < 4; ++j)
                outF[((size_t)(b * Nn + s0 + s)) * Nn + 256 * j + tid] = acc[s][j] * iz;
        }
    } else {
#pragma unroll
        for (int s = 0; s < 16; ++s)
#pragma unroll
            for (int j = 0; j < 4; ++j)
                g_P[((size_t)(b * Nn + s0 + s)) * Nn + 256 * j + tid] = acc[s][j];
    }
}

// ---------------- host orchestration ----------------
extern "C" void kernel_launch(void* const* d_in, const int* in_sizes, int n_in,
                              void* d_out, int out_size) {
    const float* x_s   = (const float*)d_in[0];
    const int*   ei_s  = (const int*)d_in[1];
    const float* x_t   = (const float*)d_in[2];
    const int*   ei_t  = (const int*)d_in[3];
    const float* W1s   = (const float*)d_in[4];
    const float* W1n   = (const float*)d_in[5];
    const float* b1    = (const float*)d_in[6];
    const float* W2s   = (const float*)d_in[7];
    const float* W2n   = (const float*)d_in[8];
    const float* b2v   = (const float*)d_in[9];
    const float* Wm1   = (const float*)d_in[10];
    const float* bm1v  = (const float*)d_in[11];
    const float* Wm2   = (const float*)d_in[12];
    const float* bm2v  = (const float*)d_in[13];
    const float* rsteps = (const float*)d_in[14];
    float* out = (float*)d_out;

    // psi1
    k_zero_agg1<<<1024, 256>>>();
    k_scatter128<<<dim3(Ee * 32 / 256, 2), 256>>>(x_s, x_t, ei_s, ei_t);
    k_psi1<<<dim3(BN / 64, 2, 2), 256>>>(x_s, x_t, W1s, W1n, b1);

    // S_hat (tensor-core) + fused initial stats/P/S_0
    k_shat<<<dim3(Nn / 128, Nn / 128, Bb), 256>>>();
    k_stats0<<<BN, 256>>>(out);

    for (int step = 0; step < NSTEPS; ++step) {
        const float* rs = rsteps + (size_t)step * Bb * Nn * Rr;

        // zero rt + aggR; o_s path -> A_s[step]
        k_zeroRall<<<128, 256>>>();
        k_scatter16<<<Ee * 4 / 256, 256>>>(0, rs, ei_s);
        k_psi2<<<BN / 16, 256>>>(0, rs, W2s, W2n, b2v, Wm1, 1, bm1v, 0, step);

        // r_t = softmax(S_hat)^T @ r_s  (uses cached P + invZ)
        k_rt<<<dim3(8, 8, Bb), 128>>>(rs);

        // o_t path -> B_t
        k_zeroAggR<<<64, 256>>>();
        k_scatter16<<<Ee * 4 / 256, 256>>>(1, rs, ei_t);
        k_psi2<<<BN / 16, 256>>>(1, rs, W2s, W2n, b2v, Wm1, 0, bm1v, 1, step);

        // fused: S_hat += upd, row stats, P/invZ (mid) or S_L (final)
        int fin = (step == NSTEPS - 1);
        k_updstats2<<<dim3(Nn / 16, Bb), 256>>>(step, Wm2, bm2v,
            fin ? (out + (size_t)Bb * Nn * Nn) : (float*)nullptr, fin);
    }
}

// round 15
// speedup vs baseline: 1.2009x; 1.2009x over previous
#include <cuda_runtime.h>

#define Bb 4
#define Nn 1024
#define BN 4096
#define Ff 128
#define Rr 16
#define Ee 65536
#define NSTEPS 2

// ---------------- scratch (device globals; no runtime allocation) ----------------
__device__ float g_agg1[2][BN * Ff];           // psi1 neighbor aggregation (s, t)
__device__ float g_h[2][BN * Ff];              // h_s, h_t
__device__ float g_Shat[(size_t)Bb * Nn * Nn]; // 16 MB logits
__device__ float g_P[(size_t)Bb * Nn * Nn];    // 16 MB exp(Shat - m) cache
__device__ float g_invZ[BN];                   // 1/row sum-exp
__device__ float g_rt[BN * Rr];                // r_t
__device__ float g_aggR[BN * Rr];              // psi2 aggregation scratch
__device__ float g_As[NSTEPS][BN * Rr];        // A_s = o_s@Wm1 + bm1 per step
__device__ float g_Bt[BN * Rr];                // B_t = o_t@Wm1

__device__ __forceinline__ void red_add_f4(float* p, float4 v) {
    asm volatile("red.global.add.v4.f32 [%0], {%1,%2,%3,%4};"
                 :: "l"(p), "f"(v.x), "f"(v.y), "f"(v.z), "f"(v.w) : "memory");
}

__device__ __forceinline__ unsigned f2tf32(float x) {
    unsigned r;
    asm("cvt.rna.tf32.f32 %0, %1;" : "=r"(r) : "f"(x));
    return r;
}

__device__ __forceinline__ void mma_tf32(float* c, const unsigned* a, const unsigned* b) {
    asm volatile(
        "mma.sync.aligned.m16n8k8.row.col.f32.tf32.tf32.f32 "
        "{%0,%1,%2,%3}, {%4,%5,%6,%7}, {%8,%9}, {%0,%1,%2,%3};"
        : "+f"(c[0]), "+f"(c[1]), "+f"(c[2]), "+f"(c[3])
        : "r"(a[0]), "r"(a[1]), "r"(a[2]), "r"(a[3]), "r"(b[0]), "r"(b[1]));
}

// ---------------- zero kernels ----------------
__global__ void k_zero_agg1() {
    int i = blockIdx.x * blockDim.x + threadIdx.x;      // 262144 float4
    ((float4*)g_agg1)[i] = make_float4(0.f, 0.f, 0.f, 0.f);
}

__global__ void k_zeroRall() {                          // zero rt + aggR (32768 float4)
    int i = blockIdx.x * blockDim.x + threadIdx.x;
    if (i < 16384) ((float4*)g_rt)[i] = make_float4(0.f, 0.f, 0.f, 0.f);
    else ((float4*)g_aggR)[i - 16384] = make_float4(0.f, 0.f, 0.f, 0.f);
}

__global__ void k_zeroAggR() {                          // 16384 float4
    int i = blockIdx.x * blockDim.x + threadIdx.x;
    ((float4*)g_aggR)[i] = make_float4(0.f, 0.f, 0.f, 0.f);
}

// ---------------- psi1 aggregation: agg[dst] += x[src] (vector red) ----------------
__global__ void k_scatter128(const float* __restrict__ xs, const float* __restrict__ xt,
                             const int* __restrict__ eis, const int* __restrict__ eit) {
    int g = blockIdx.y;
    const float* x = g ? xt : xs;
    const int* ei = g ? eit : eis;
    float* agg = g_agg1[g];
    int idx = blockIdx.x * blockDim.x + threadIdx.x;    // < E*32
    int e = idx >> 5;
    int q = idx & 31;
    int src = ei[e];
    int dst = ei[Ee + e];
    float4 v = *(const float4*)&x[(size_t)src * Ff + 4 * q];
    red_add_f4(&agg[(size_t)dst * Ff + 4 * q], v);
}

// ---------------- psi1 GEMM: h = relu(x@Ws + agg@Wn + b1) ----------------
// BM=64, BN=64, K=256 (x||agg phases); 256 threads; 4x4 micro; double-buffered
__global__ __launch_bounds__(256) void k_psi1(
    const float* __restrict__ xs, const float* __restrict__ xt,
    const float* __restrict__ Ws, const float* __restrict__ Wn,
    const float* __restrict__ bias) {
    __shared__ float sA[2][16][68];
    __shared__ float sW[2][16][68];

    int g = blockIdx.z;
    int c0 = blockIdx.y * 64;
    int row0 = blockIdx.x * 64;
    const float* x = g ? xt : xs;
    const float* agg = g_agg1[g];
    float* h = g_h[g];

    int tid = threadIdx.x;
    int tx = tid & 15, ty = tid >> 4;
    int ar_ = tid & 63, ak = (tid >> 6) * 4;
    int wr = tid >> 4, wc = 4 * (tid & 15);

    float acc[4][4];
#pragma unroll
    for (int i = 0; i < 4; ++i)
#pragma unroll
        for (int j = 0; j < 4; ++j) acc[i][j] = 0.f;

#define LOAD_A(c) (*(const float4*)&(((c) < 8) ? x : agg)[(size_t)(row0 + ar_) * Ff + (((c)*16) & 127) + ak])
#define LOAD_W(c) (*(const float4*)&(((c) < 8) ? Ws : Wn)[(size_t)((((c)*16) & 127) + wr) * Ff + c0 + wc])

    float4 va = LOAD_A(0);
    float4 vw = LOAD_W(0);
    sA[0][ak + 0][ar_] = va.x; sA[0][ak + 1][ar_] = va.y;
    sA[0][ak + 2][ar_] = va.z; sA[0][ak + 3][ar_] = va.w;
    *(float4*)&sW[0][wr][wc] = vw;
    va = LOAD_A(1);
    vw = LOAD_W(1);
    __syncthreads();

    for (int c = 0; c < 16; ++c) {
        int cur = c & 1;
        if (c < 15) {
            int nxt = cur ^ 1;
            sA[nxt][ak + 0][ar_] = va.x; sA[nxt][ak + 1][ar_] = va.y;
            sA[nxt][ak + 2][ar_] = va.z; sA[nxt][ak + 3][ar_] = va.w;
            *(float4*)&sW[nxt][wr][wc] = vw;
        }
        if (c < 14) {
            va = LOAD_A(c + 2);
            vw = LOAD_W(c + 2);
        }
#pragma unroll
        for (int k = 0; k < 16; ++k) {
            float4 a = *(float4*)&sA[cur][k][4 * ty];
            float4 w = *(float4*)&sW[cur][k][4 * tx];
            float arr[4] = {a.x, a.y, a.z, a.w};
#pragma unroll
            for (int i = 0; i < 4; ++i) {
                acc[i][0] += arr[i] * w.x; acc[i][1] += arr[i] * w.y;
                acc[i][2] += arr[i] * w.z; acc[i][3] += arr[i] * w.w;
            }
        }
        __syncthreads();
    }
#undef LOAD_A
#undef LOAD_W

    float4 bv = *(const float4*)&bias[c0 + 4 * tx];
#pragma unroll
    for (int i = 0; i < 4; ++i) {
        int row = row0 + 4 * ty + i;
        float4 o;
        o.x = fmaxf(acc[i][0] + bv.x, 0.f);
        o.y = fmaxf(acc[i][1] + bv.y, 0.f);
        o.z = fmaxf(acc[i][2] + bv.z, 0.f);
        o.w = fmaxf(acc[i][3] + bv.w, 0.f);
        *(float4*)&h[(size_t)row * Ff + c0 + 4 * tx] = o;
    }
}

// ---------------- S_hat = h_s @ h_t^T per batch (3xTF32 tensor-core) ----------------
// 128x128 tile, 8 warps (2x4), warp tile 64x32; m16n8k8 atoms; BK=16, 8 chunks
__global__ __launch_bounds__(256, 2) void k_shat() {
    __shared__ float sAb[128][20];   // A hi (tf32-rounded)
    __shared__ float sAl[128][20];   // A lo
    __shared__ float sBb[128][20];   // B hi
    __shared__ float sBl[128][20];   // B lo

    int b = blockIdx.z;
    int t0 = blockIdx.x * 128;
    int s0 = blockIdx.y * 128;
    const float* hs = g_h[0] + (size_t)b * Nn * Ff;
    const float* ht = g_h[1] + (size_t)b * Nn * Ff;

    int tid = threadIdx.x;
    int lane = tid & 31;
    int w = tid >> 5;
    int wm = w >> 2;          // 0..1 : s-offset 64*wm
    int wn = w & 3;           // 0..3 : t-offset 32*wn
    int qr = lane >> 2;       // 0..7
    int qc = lane & 3;        // 0..3

    int lrow = tid >> 1;      // 0..127
    int lcol = (tid & 1) * 8; // 0 or 8

    const float* pa = &hs[(size_t)(s0 + lrow) * Ff + lcol];
    const float* pb = &ht[(size_t)(t0 + lrow) * Ff + lcol];

    float acc[4][4][4];       // [ma][na][reg]
#pragma unroll
    for (int i = 0; i < 4; ++i)
#pragma unroll
        for (int j = 0; j < 4; ++j)
#pragma unroll
            for (int r = 0; r < 4; ++r) acc[i][j][r] = 0.f;

    // preload chunk 0
    float4 ga0 = *(const float4*)pa;
    float4 ga1 = *(const float4*)(pa + 4);
    float4 gb0 = *(const float4*)pb;
    float4 gb1 = *(const float4*)(pb + 4);

    for (int c = 0; c < 8; ++c) {
        __syncthreads();
        {
            float av[8] = {ga0.x, ga0.y, ga0.z, ga0.w, ga1.x, ga1.y, ga1.z, ga1.w};
            float bv[8] = {gb0.x, gb0.y, gb0.z, gb0.w, gb1.x, gb1.y, gb1.z, gb1.w};
#pragma unroll
            for (int i = 0; i < 8; ++i) {
                unsigned hb = f2tf32(av[i]);
                float hf = __uint_as_float(hb);
                sAb[lrow][lcol + i] = hf;
                sAl[lrow][lcol + i] = __uint_as_float(f2tf32(av[i] - hf));
                unsigned hb2 = f2tf32(bv[i]);
                float hf2 = __uint_as_float(hb2);
                sBb[lrow][lcol + i] = hf2;
                sBl[lrow][lcol + i] = __uint_as_float(f2tf32(bv[i] - hf2));
            }
        }
        __syncthreads();

        if (c < 7) {
            const float* npa = pa + 16 * (c + 1);
            const float* npb = pb + 16 * (c + 1);
            ga0 = *(const float4*)npa;
            ga1 = *(const float4*)(npa + 4);
            gb0 = *(const float4*)npb;
            gb1 = *(const float4*)(npb + 4);
        }

#pragma unroll
        for (int s8 = 0; s8 < 2; ++s8) {
            int k0 = 8 * s8;
            unsigned Bbf[4][2], Blf[4][2];
#pragma unroll
            for (int na = 0; na < 4; ++na) {
                int trow = 32 * wn + 8 * na + qr;
                Bbf[na][0] = __float_as_uint(sBb[trow][k0 + qc]);
                Bbf[na][1] = __float_as_uint(sBb[trow][k0 + 4 + qc]);
                Blf[na][0] = __float_as_uint(sBl[trow][k0 + qc]);
                Blf[na][1] = __float_as_uint(sBl[trow][k0 + 4 + qc]);
            }
#pragma unroll
            for (int ma = 0; ma < 4; ++ma) {
                int ar0 = 64 * wm + 16 * ma + qr;
                unsigned Abf[4], Alf[4];
                Abf[0] = __float_as_uint(sAb[ar0][k0 + qc]);
                Abf[1] = __float_as_uint(sAb[ar0 + 8][k0 + qc]);
                Abf[2] = __float_as_uint(sAb[ar0][k0 + 4 + qc]);
                Abf[3] = __float_as_uint(sAb[ar0 + 8][k0 + 4 + qc]);
                Alf[0] = __float_as_uint(sAl[ar0][k0 + qc]);
                Alf[1] = __float_as_uint(sAl[ar0 + 8][k0 + qc]);
                Alf[2] = __float_as_uint(sAl[ar0][k0 + 4 + qc]);
                Alf[3] = __float_as_uint(sAl[ar0 + 8][k0 + 4 + qc]);
#pragma unroll
                for (int na = 0; na < 4; ++na) {
                    mma_tf32(acc[ma][na], Abf, Blf[na]);   // hi*lo
                    mma_tf32(acc[ma][na], Alf, Bbf[na]);   // lo*hi
                    mma_tf32(acc[ma][na], Abf, Bbf[na]);   // hi*hi
                }
            }
        }
    }

#pragma unroll
    for (int ma = 0; ma < 4; ++ma) {
#pragma unroll
        for (int na = 0; na < 4; ++na) {
            int row = s0 + 64 * wm + 16 * ma + qr;
            int col = t0 + 32 * wn + 8 * na + 2 * qc;
            float* d0 = &g_Shat[((size_t)(b * Nn + row)) * Nn + col];
            float* d1 = &g_Shat[((size_t)(b * Nn + row + 8)) * Nn + col];
            *(float2*)d0 = make_float2(acc[ma][na][0], acc[ma][na][1]);
            *(float2*)d1 = make_float2(acc[ma][na][2], acc[ma][na][3]);
        }
    }
}

// ---------------- initial stats: writes P, invZ, and S_0 in ONE pass ----------------
__global__ __launch_bounds__(256) void k_stats0(float* __restrict__ out) {
    int row = blockIdx.x;
    int tid = threadIdx.x;
    const float4* p = (const float4*)(g_Shat + (size_t)row * Nn);
    float4 v = p[tid];
    float m = fmaxf(fmaxf(v.x, v.y), fmaxf(v.z, v.w));
#pragma unroll
    for (int o = 16; o > 0; o >>= 1) m = fmaxf(m, __shfl_xor_sync(0xffffffffu, m, o));
    __shared__ float sred[8];
    __shared__ float sbc;
    int wid = tid >> 5, lane = tid & 31;
    if (lane == 0) sred[wid] = m;
    __syncthreads();
    if (tid == 0) {
        float mm = sred[0];
#pragma unroll
        for (int i = 1; i < 8; ++i) mm = fmaxf(mm, sred[i]);
        sbc = mm;
    }
    __syncthreads();
    m = sbc;
    float4 e;
    e.x = __expf(v.x - m);
    e.y = __expf(v.y - m);
    e.z = __expf(v.z - m);
    e.w = __expf(v.w - m);
    ((float4*)(g_P + (size_t)row * Nn))[tid] = e;
    float s = e.x + e.y + e.z + e.w;
#pragma unroll
    for (int o = 16; o > 0; o >>= 1) s += __shfl_xor_sync(0xffffffffu, s, o);
    if (lane == 0) sred[wid] = s;
    __syncthreads();
    if (tid == 0) {
        float ss = 0.f;
#pragma unroll
        for (int i = 0; i < 8; ++i) ss += sred[i];
        float iz = 1.0f / ss;
        sbc = iz;
        g_invZ[row] = iz;
    }
    __syncthreads();
    float iz = sbc;
    float4 o;
    o.x = e.x * iz; o.y = e.y * iz; o.z = e.z * iz; o.w = e.w * iz;
    ((float4*)(out + (size_t)row * Nn))[tid] = o;
}

// ---------------- mid-step stats: writes P + invZ ----------------
__global__ __launch_bounds__(256) void k_stats() {
    int row = blockIdx.x;
    int tid = threadIdx.x;
    const float4* p = (const float4*)(g_Shat + (size_t)row * Nn);
    float4 v = p[tid];
    float m = fmaxf(fmaxf(v.x, v.y), fmaxf(v.z, v.w));
#pragma unroll
    for (int o = 16; o > 0; o >>= 1) m = fmaxf(m, __shfl_xor_sync(0xffffffffu, m, o));
    __shared__ float sred[8];
    __shared__ float sbc;
    int wid = tid >> 5, lane = tid & 31;
    if (lane == 0) sred[wid] = m;
    __syncthreads();
    if (tid == 0) {
        float mm = sred[0];
#pragma unroll
        for (int i = 1; i < 8; ++i) mm = fmaxf(mm, sred[i]);
        sbc = mm;
    }
    __syncthreads();
    m = sbc;
    float4 e;
    e.x = __expf(v.x - m);
    e.y = __expf(v.y - m);
    e.z = __expf(v.z - m);
    e.w = __expf(v.w - m);
    ((float4*)(g_P + (size_t)row * Nn))[tid] = e;
    float s = e.x + e.y + e.z + e.w;
#pragma unroll
    for (int o = 16; o > 0; o >>= 1) s += __shfl_xor_sync(0xffffffffu, s, o);
    if (lane == 0) sred[wid] = s;
    __syncthreads();
    if (tid == 0) {
        float ss = 0.f;
#pragma unroll
        for (int i = 0; i < 8; ++i) ss += sred[i];
        g_invZ[row] = 1.0f / ss;
    }
}

// ---------------- final stats: reads Shat, writes normalized S_L directly ----------------
__global__ __launch_bounds__(256) void k_statsF(float* __restrict__ out) {
    int row = blockIdx.x;
    int tid = threadIdx.x;
    const float4* p = (const float4*)(g_Shat + (size_t)row * Nn);
    float4 v = p[tid];
    float m = fmaxf(fmaxf(v.x, v.y), fmaxf(v.z, v.w));
#pragma unroll
    for (int o = 16; o > 0; o >>= 1) m = fmaxf(m, __shfl_xor_sync(0xffffffffu, m, o));
    __shared__ float sred[8];
    __shared__ float sbc;
    int wid = tid >> 5, lane = tid & 31;
    if (lane == 0) sred[wid] = m;
    __syncthreads();
    if (tid == 0) {
        float mm = sred[0];
#pragma unroll
        for (int i = 1; i < 8; ++i) mm = fmaxf(mm, sred[i]);
        sbc = mm;
    }
    __syncthreads();
    m = sbc;
    float4 e;
    e.x = __expf(v.x - m);
    e.y = __expf(v.y - m);
    e.z = __expf(v.z - m);
    e.w = __expf(v.w - m);
    float s = e.x + e.y + e.z + e.w;
#pragma unroll
    for (int o = 16; o > 0; o >>= 1) s += __shfl_xor_sync(0xffffffffu, s, o);
    if (lane == 0) sred[wid] = s;
    __syncthreads();
    if (tid == 0) {
        float ss = 0.f;
#pragma unroll
        for (int i = 0; i < 8; ++i) ss += sred[i];
        sbc = 1.0f / ss;
    }
    __syncthreads();
    float iz = sbc;
    float4 o;
    o.x = e.x * iz; o.y = e.y * iz; o.z = e.z * iz; o.w = e.w * iz;
    ((float4*)(out + (size_t)row * Nn))[tid] = o;
}

// ---------------- r_t = softmax(S_hat)^T @ r_s  (uses cached P) ----------------
// grid (t_chunks=4 x 256, s_chunks=16 x 64, B); 256 threads; 64 s-iters/thread
__global__ __launch_bounds__(256) void k_rt(const float* __restrict__ rs) {
    __shared__ float s_rs[64][Rr];
    __shared__ float s_iz[64];
    int b = blockIdx.z;
    int t0 = blockIdx.x * 256;
    int s0 = blockIdx.y * 64;
    int tid = threadIdx.x;
#pragma unroll
    for (int i = 0; i < 4; ++i) {
        int lin = tid + 256 * i;
        int r = lin >> 4, c = lin & 15;
        s_rs[r][c] = rs[((size_t)(b * Nn + s0 + r)) * Rr + c];
    }
    if (tid < 64) s_iz[tid] = g_invZ[b * Nn + s0 + tid];
    __syncthreads();

    int t = t0 + tid;
    float acc[Rr];
#pragma unroll
    for (int r = 0; r < Rr; ++r) acc[r] = 0.f;
    const float* sp = g_P + ((size_t)(b * Nn + s0)) * Nn + t;
#pragma unroll 8
    for (int s = 0; s < 64; ++s) {
        float w = sp[(size_t)s * Nn] * s_iz[s];
#pragma unroll
        for (int r = 0; r < Rr; ++r) acc[r] += w * s_rs[s][r];
    }
    float* rt = g_rt + (size_t)(b * Nn + t) * Rr;
#pragma unroll
    for (int q = 0; q < 4; ++q)
        red_add_f4(&rt[4 * q], make_float4(acc[4 * q], acc[4 * q + 1], acc[4 * q + 2], acc[4 * q + 3]));
}

// ---------------- psi2 aggregation (R=16, vector red) ----------------
__global__ void k_scatter16(int src_is_rt, const float* __restrict__ rext,
                            const int* __restrict__ ei) {
    int idx = blockIdx.x * blockDim.x + threadIdx.x;   // < E*4
    int e = idx >> 2;
    int q = idx & 3;
    const float* src = src_is_rt ? g_rt : rext;
    float4 v = *(const float4*)&src[(size_t)ei[e] * Rr + 4 * q];
    red_add_f4(&g_aggR[(size_t)ei[Ee + e] * Rr + 4 * q], v);
}

// ---------------- psi2 + Wm1 projection fused ----------------
__global__ __launch_bounds__(256) void k_psi2(
    int src_is_rt, const float* __restrict__ rext,
    const float* __restrict__ W2s, const float* __restrict__ W2n,
    const float* __restrict__ b2v, const float* __restrict__ Wm1,
    int use_bm1, const float* __restrict__ bm1v, int out_is_B, int step) {
    __shared__ float sr[16][17], sg[16][17], so[16][17];
    __shared__ float sWs[256], sWn[256], sWm[256];
    int tid = threadIdx.x;
    int r = tid >> 4, j = tid & 15;
    int row0 = blockIdx.x * 16;
    const float* src = src_is_rt ? g_rt : rext;
    sr[r][j] = src[(size_t)(row0 + r) * Rr + j];
    sg[r][j] = g_aggR[(size_t)(row0 + r) * Rr + j];
    sWs[tid] = W2s[tid];
    sWn[tid] = W2n[tid];
    sWm[tid] = Wm1[tid];
    __syncthreads();
    float acc = b2v[j];
#pragma unroll
    for (int k = 0; k < 16; ++k)
        acc += sr[r][k] * sWs[k * 16 + j] + sg[r][k] * sWn[k * 16 + j];
    so[r][j] = fmaxf(acc, 0.f);
    __syncthreads();
    float a2 = use_bm1 ? bm1v[j] : 0.f;
#pragma unroll
    for (int k = 0; k < 16; ++k) a2 += so[r][k] * sWm[k * 16 + j];
    float* dst = out_is_B ? g_Bt : g_As[step];
    dst[(size_t)(row0 + r) * Rr + j] = a2;
}

// ---------------- S_hat += sum_k relu(A_s[s,k]-B_t[t,k])*Wm2[k] + bm2 ----------------
// grid (t_chunks=4, s_tiles=64, B), 256 threads (tiled Bt reads: 16 MB total)
__global__ __launch_bounds__(256) void k_upd(int step, const float* __restrict__ Wm2,
                                             const float* __restrict__ bm2v) {
    __shared__ float sA[16][16];
    __shared__ float swm[16];
    int b = blockIdx.z;
    int s0 = blockIdx.y * 16;
    int t0 = blockIdx.x * 256;
    int tid = threadIdx.x;
    sA[tid >> 4][tid & 15] = g_As[step][(size_t)(b * Nn + s0 + (tid >> 4)) * Rr + (tid & 15)];
    if (tid < 16) swm[tid] = Wm2[tid];
    float bb = bm2v[0];
    int t = t0 + tid;
    float Bk[16];
    const float4* bp = (const float4*)&g_Bt[(size_t)(b * Nn + t) * Rr];
    float4 b0 = bp[0], b1 = bp[1], b2 = bp[2], b3 = bp[3];
    Bk[0] = b0.x; Bk[1] = b0.y; Bk[2] = b0.z; Bk[3] = b0.w;
    Bk[4] = b1.x; Bk[5] = b1.y; Bk[6] = b1.z; Bk[7] = b1.w;
    Bk[8] = b2.x; Bk[9] = b2.y; Bk[10] = b2.z; Bk[11] = b2.w;
    Bk[12] = b3.x; Bk[13] = b3.y; Bk[14] = b3.z; Bk[15] = b3.w;
    __syncthreads();
    float* shp = g_Shat + ((size_t)(b * Nn + s0)) * Nn + t;
#pragma unroll
    for (int s = 0; s < 16; ++s) {
        float acc = bb;
#pragma unroll
        for (int k = 0; k < 16; ++k)
            acc += fmaxf(sA[s][k] - Bk[k], 0.f) * swm[k];
        shp[(size_t)s * Nn] += acc;
    }
}

// ---------------- host orchestration ----------------
extern "C" void kernel_launch(void* const* d_in, const int* in_sizes, int n_in,
                              void* d_out, int out_size) {
    const float* x_s   = (const float*)d_in[0];
    const int*   ei_s  = (const int*)d_in[1];
    const float* x_t   = (const float*)d_in[2];
    const int*   ei_t  = (const int*)d_in[3];
    const float* W1s   = (const float*)d_in[4];
    const float* W1n   = (const float*)d_in[5];
    const float* b1    = (const float*)d_in[6];
    const float* W2s   = (const float*)d_in[7];
    const float* W2n   = (const float*)d_in[8];
    const float* b2v   = (const float*)d_in[9];
    const float* Wm1   = (const float*)d_in[10];
    const float* bm1v  = (const float*)d_in[11];
    const float* Wm2   = (const float*)d_in[12];
    const float* bm2v  = (const float*)d_in[13];
    const float* rsteps = (const float*)d_in[14];
    float* out = (float*)d_out;

    // psi1
    k_zero_agg1<<<1024, 256>>>();
    k_scatter128<<<dim3(Ee * 32 / 256, 2), 256>>>(x_s, x_t, ei_s, ei_t);
    k_psi1<<<dim3(BN / 64, 2, 2), 256>>>(x_s, x_t, W1s, W1n, b1);

    // S_hat (tensor-core) + fused initial stats/P/S_0
    k_shat<<<dim3(Nn / 128, Nn / 128, Bb), 256>>>();
    k_stats0<<<BN, 256>>>(out);

    for (int step = 0; step < NSTEPS; ++step) {
        const float* rs = rsteps + (size_t)step * Bb * Nn * Rr;

        // zero rt + aggR; o_s path -> A_s[step]
        k_zeroRall<<<128, 256>>>();
        k_scatter16<<<Ee * 4 / 256, 256>>>(0, rs, ei_s);
        k_psi2<<<BN / 16, 256>>>(0, rs, W2s, W2n, b2v, Wm1, 1, bm1v, 0, step);

        // r_t = softmax(S_hat)^T @ r_s  (uses cached P + invZ)
        k_rt<<<dim3(4, 16, Bb), 256>>>(rs);

        // o_t path -> B_t
        k_zeroAggR<<<64, 256>>>();
        k_scatter16<<<Ee * 4 / 256, 256>>>(1, rs, ei_t);
        k_psi2<<<BN / 16, 256>>>(1, rs, W2s, W2n, b2v, Wm1, 0, bm1v, 1, step);

        // S_hat += upd ; then stats (mid writes P+invZ, final writes S_L directly)
        k_upd<<<dim3(4, 64, Bb), 256>>>(step, Wm2, bm2v);
        if (step == NSTEPS - 1)
            k_statsF<<<BN, 256>>>(out + (size_t)Bb * Nn * Nn);
        else
            k_stats<<<BN, 256>>>();
    }
}

// round 16
// speedup vs baseline: 1.2382x; 1.0310x over previous
#include <cuda_runtime.h>

#define Bb 4
#define Nn 1024
#define BN 4096
#define Ff 128
#define Rr 16
#define Ee 65536
#define NSTEPS 2

// ---------------- scratch (device globals; no runtime allocation) ----------------
__device__ float g_agg1[2][BN * Ff];           // psi1 neighbor aggregation (s, t)
__device__ float g_h[2][BN * Ff];              // h_s, h_t
__device__ float g_Shat[(size_t)Bb * Nn * Nn]; // 16 MB logits
__device__ float g_P[(size_t)Bb * Nn * Nn];    // 16 MB exp(Shat - m) cache
__device__ float g_invZ[BN];                   // 1/row sum-exp
__device__ float g_rt[BN * Rr];                // r_t
__device__ float g_aggR[BN * Rr];              // psi2 aggregation scratch (t path)
__device__ float g_aggR2[NSTEPS][BN * Rr];     // psi2 aggregation (s path, per step)
__device__ float g_As[NSTEPS][BN * Rr];        // A_s = o_s@Wm1 + bm1 per step
__device__ float g_Bt[BN * Rr];                // B_t = o_t@Wm1

__device__ __forceinline__ void red_add_f4(float* p, float4 v) {
    asm volatile("red.global.add.v4.f32 [%0], {%1,%2,%3,%4};"
                 :: "l"(p), "f"(v.x), "f"(v.y), "f"(v.z), "f"(v.w) : "memory");
}

__device__ __forceinline__ unsigned f2tf32(float x) {
    unsigned r;
    asm("cvt.rna.tf32.f32 %0, %1;" : "=r"(r) : "f"(x));
    return r;
}

__device__ __forceinline__ void mma_tf32(float* c, const unsigned* a, const unsigned* b) {
    asm volatile(
        "mma.sync.aligned.m16n8k8.row.col.f32.tf32.tf32.f32 "
        "{%0,%1,%2,%3}, {%4,%5,%6,%7}, {%8,%9}, {%0,%1,%2,%3};"
        : "+f"(c[0]), "+f"(c[1]), "+f"(c[2]), "+f"(c[3])
        : "r"(a[0]), "r"(a[1]), "r"(a[2]), "r"(a[3]), "r"(b[0]), "r"(b[1]));
}

// ---------------- single up-front zero: agg1 + rt + aggR + aggR2 ----------------
__global__ void k_zero_all() {
    int i = blockIdx.x * blockDim.x + threadIdx.x;   // 327680 float4
    float4 z = make_float4(0.f, 0.f, 0.f, 0.f);
    if (i < 262144) ((float4*)g_agg1)[i] = z;
    else if (i < 278528) ((float4*)g_rt)[i - 262144] = z;
    else if (i < 294912) ((float4*)g_aggR)[i - 278528] = z;
    else ((float4*)g_aggR2)[i - 294912] = z;
}

// ---------------- psi1 aggregation: agg[dst] += x[src] (vector red) ----------------
__global__ void k_scatter128(const float* __restrict__ xs, const float* __restrict__ xt,
                             const int* __restrict__ eis, const int* __restrict__ eit) {
    int g = blockIdx.y;
    const float* x = g ? xt : xs;
    const int* ei = g ? eit : eis;
    float* agg = g_agg1[g];
    int idx = blockIdx.x * blockDim.x + threadIdx.x;    // < E*32
    int e = idx >> 5;
    int q = idx & 31;
    int src = ei[e];
    int dst = ei[Ee + e];
    float4 v = *(const float4*)&x[(size_t)src * Ff + 4 * q];
    red_add_f4(&agg[(size_t)dst * Ff + 4 * q], v);
}

// ---------------- psi1 GEMM: h = relu(x@Ws + agg@Wn + b1) ----------------
__global__ __launch_bounds__(256) void k_psi1(
    const float* __restrict__ xs, const float* __restrict__ xt,
    const float* __restrict__ Ws, const float* __restrict__ Wn,
    const float* __restrict__ bias) {
    __shared__ float sA[2][16][68];
    __shared__ float sW[2][16][68];

    int g = blockIdx.z;
    int c0 = blockIdx.y * 64;
    int row0 = blockIdx.x * 64;
    const float* x = g ? xt : xs;
    const float* agg = g_agg1[g];
    float* h = g_h[g];

    int tid = threadIdx.x;
    int tx = tid & 15, ty = tid >> 4;
    int ar_ = tid & 63, ak = (tid >> 6) * 4;
    int wr = tid >> 4, wc = 4 * (tid & 15);

    float acc[4][4];
#pragma unroll
    for (int i = 0; i < 4; ++i)
#pragma unroll
        for (int j = 0; j < 4; ++j) acc[i][j] = 0.f;

#define LOAD_A(c) (*(const float4*)&(((c) < 8) ? x : agg)[(size_t)(row0 + ar_) * Ff + (((c)*16) & 127) + ak])
#define LOAD_W(c) (*(const float4*)&(((c) < 8) ? Ws : Wn)[(size_t)((((c)*16) & 127) + wr) * Ff + c0 + wc])

    float4 va = LOAD_A(0);
    float4 vw = LOAD_W(0);
    sA[0][ak + 0][ar_] = va.x; sA[0][ak + 1][ar_] = va.y;
    sA[0][ak + 2][ar_] = va.z; sA[0][ak + 3][ar_] = va.w;
    *(float4*)&sW[0][wr][wc] = vw;
    va = LOAD_A(1);
    vw = LOAD_W(1);
    __syncthreads();

    for (int c = 0; c < 16; ++c) {
        int cur = c & 1;
        if (c < 15) {
            int nxt = cur ^ 1;
            sA[nxt][ak + 0][ar_] = va.x; sA[nxt][ak + 1][ar_] = va.y;
            sA[nxt][ak + 2][ar_] = va.z; sA[nxt][ak + 3][ar_] = va.w;
            *(float4*)&sW[nxt][wr][wc] = vw;
        }
        if (c < 14) {
            va = LOAD_A(c + 2);
            vw = LOAD_W(c + 2);
        }
#pragma unroll
        for (int k = 0; k < 16; ++k) {
            float4 a = *(float4*)&sA[cur][k][4 * ty];
            float4 w = *(float4*)&sW[cur][k][4 * tx];
            float arr[4] = {a.x, a.y, a.z, a.w};
#pragma unroll
            for (int i = 0; i < 4; ++i) {
                acc[i][0] += arr[i] * w.x; acc[i][1] += arr[i] * w.y;
                acc[i][2] += arr[i] * w.z; acc[i][3] += arr[i] * w.w;
            }
        }
        __syncthreads();
    }
#undef LOAD_A
#undef LOAD_W

    float4 bv = *(const float4*)&bias[c0 + 4 * tx];
#pragma unroll
    for (int i = 0; i < 4; ++i) {
        int row = row0 + 4 * ty + i;
        float4 o;
        o.x = fmaxf(acc[i][0] + bv.x, 0.f);
        o.y = fmaxf(acc[i][1] + bv.y, 0.f);
        o.z = fmaxf(acc[i][2] + bv.z, 0.f);
        o.w = fmaxf(acc[i][3] + bv.w, 0.f);
        *(float4*)&h[(size_t)row * Ff + c0 + 4 * tx] = o;
    }
}

// ---------------- S_hat = h_s @ h_t^T per batch (3xTF32 tensor-core) ----------------
__global__ __launch_bounds__(256, 2) void k_shat() {
    __shared__ float sAb[128][20];
    __shared__ float sAl[128][20];
    __shared__ float sBb[128][20];
    __shared__ float sBl[128][20];

    int b = blockIdx.z;
    int t0 = blockIdx.x * 128;
    int s0 = blockIdx.y * 128;
    const float* hs = g_h[0] + (size_t)b * Nn * Ff;
    const float* ht = g_h[1] + (size_t)b * Nn * Ff;

    int tid = threadIdx.x;
    int lane = tid & 31;
    int w = tid >> 5;
    int wm = w >> 2;
    int wn = w & 3;
    int qr = lane >> 2;
    int qc = lane & 3;

    int lrow = tid >> 1;
    int lcol = (tid & 1) * 8;

    const float* pa = &hs[(size_t)(s0 + lrow) * Ff + lcol];
    const float* pb = &ht[(size_t)(t0 + lrow) * Ff + lcol];

    float acc[4][4][4];
#pragma unroll
    for (int i = 0; i < 4; ++i)
#pragma unroll
        for (int j = 0; j < 4; ++j)
#pragma unroll
            for (int r = 0; r < 4; ++r) acc[i][j][r] = 0.f;

    float4 ga0 = *(const float4*)pa;
    float4 ga1 = *(const float4*)(pa + 4);
    float4 gb0 = *(const float4*)pb;
    float4 gb1 = *(const float4*)(pb + 4);

    for (int c = 0; c < 8; ++c) {
        __syncthreads();
        {
            float av[8] = {ga0.x, ga0.y, ga0.z, ga0.w, ga1.x, ga1.y, ga1.z, ga1.w};
            float bv[8] = {gb0.x, gb0.y, gb0.z, gb0.w, gb1.x, gb1.y, gb1.z, gb1.w};
#pragma unroll
            for (int i = 0; i < 8; ++i) {
                unsigned hb = f2tf32(av[i]);
                float hf = __uint_as_float(hb);
                sAb[lrow][lcol + i] = hf;
                sAl[lrow][lcol + i] = __uint_as_float(f2tf32(av[i] - hf));
                unsigned hb2 = f2tf32(bv[i]);
                float hf2 = __uint_as_float(hb2);
                sBb[lrow][lcol + i] = hf2;
                sBl[lrow][lcol + i] = __uint_as_float(f2tf32(bv[i] - hf2));
            }
        }
        __syncthreads();

        if (c < 7) {
            const float* npa = pa + 16 * (c + 1);
            const float* npb = pb + 16 * (c + 1);
            ga0 = *(const float4*)npa;
            ga1 = *(const float4*)(npa + 4);
            gb0 = *(const float4*)npb;
            gb1 = *(const float4*)(npb + 4);
        }

#pragma unroll
        for (int s8 = 0; s8 < 2; ++s8) {
            int k0 = 8 * s8;
            unsigned Bbf[4][2], Blf[4][2];
#pragma unroll
            for (int na = 0; na < 4; ++na) {
                int trow = 32 * wn + 8 * na + qr;
                Bbf[na][0] = __float_as_uint(sBb[trow][k0 + qc]);
                Bbf[na][1] = __float_as_uint(sBb[trow][k0 + 4 + qc]);
                Blf[na][0] = __float_as_uint(sBl[trow][k0 + qc]);
                Blf[na][1] = __float_as_uint(sBl[trow][k0 + 4 + qc]);
            }
#pragma unroll
            for (int ma = 0; ma < 4; ++ma) {
                int ar0 = 64 * wm + 16 * ma + qr;
                unsigned Abf[4], Alf[4];
                Abf[0] = __float_as_uint(sAb[ar0][k0 + qc]);
                Abf[1] = __float_as_uint(sAb[ar0 + 8][k0 + qc]);
                Abf[2] = __float_as_uint(sAb[ar0][k0 + 4 + qc]);
                Abf[3] = __float_as_uint(sAb[ar0 + 8][k0 + 4 + qc]);
                Alf[0] = __float_as_uint(sAl[ar0][k0 + qc]);
                Alf[1] = __float_as_uint(sAl[ar0 + 8][k0 + qc]);
                Alf[2] = __float_as_uint(sAl[ar0][k0 + 4 + qc]);
                Alf[3] = __float_as_uint(sAl[ar0 + 8][k0 + 4 + qc]);
#pragma unroll
                for (int na = 0; na < 4; ++na) {
                    mma_tf32(acc[ma][na], Abf, Blf[na]);
                    mma_tf32(acc[ma][na], Alf, Bbf[na]);
                    mma_tf32(acc[ma][na], Abf, Bbf[na]);
                }
            }
        }
    }

#pragma unroll
    for (int ma = 0; ma < 4; ++ma) {
#pragma unroll
        for (int na = 0; na < 4; ++na) {
            int row = s0 + 64 * wm + 16 * ma + qr;
            int col = t0 + 32 * wn + 8 * na + 2 * qc;
            float* d0 = &g_Shat[((size_t)(b * Nn + row)) * Nn + col];
            float* d1 = &g_Shat[((size_t)(b * Nn + row + 8)) * Nn + col];
            *(float2*)d0 = make_float2(acc[ma][na][0], acc[ma][na][1]);
            *(float2*)d1 = make_float2(acc[ma][na][2], acc[ma][na][3]);
        }
    }
}

// ---------------- initial stats: writes P, invZ, and S_0 in ONE pass ----------------
__global__ __launch_bounds__(256) void k_stats0(float* __restrict__ out) {
    int row = blockIdx.x;
    int tid = threadIdx.x;
    const float4* p = (const float4*)(g_Shat + (size_t)row * Nn);
    float4 v = p[tid];
    float m = fmaxf(fmaxf(v.x, v.y), fmaxf(v.z, v.w));
#pragma unroll
    for (int o = 16; o > 0; o >>= 1) m = fmaxf(m, __shfl_xor_sync(0xffffffffu, m, o));
    __shared__ float sred[8];
    __shared__ float sbc;
    int wid = tid >> 5, lane = tid & 31;
    if (lane == 0) sred[wid] = m;
    __syncthreads();
    if (tid == 0) {
        float mm = sred[0];
#pragma unroll
        for (int i = 1; i < 8; ++i) mm = fmaxf(mm, sred[i]);
        sbc = mm;
    }
    __syncthreads();
    m = sbc;
    float4 e;
    e.x = __expf(v.x - m);
    e.y = __expf(v.y - m);
    e.z = __expf(v.z - m);
    e.w = __expf(v.w - m);
    ((float4*)(g_P + (size_t)row * Nn))[tid] = e;
    float s = e.x + e.y + e.z + e.w;
#pragma unroll
    for (int o = 16; o > 0; o >>= 1) s += __shfl_xor_sync(0xffffffffu, s, o);
    if (lane == 0) sred[wid] = s;
    __syncthreads();
    if (tid == 0) {
        float ss = 0.f;
#pragma unroll
        for (int i = 0; i < 8; ++i) ss += sred[i];
        float iz = 1.0f / ss;
        sbc = iz;
        g_invZ[row] = iz;
    }
    __syncthreads();
    float iz = sbc;
    float4 o;
    o.x = e.x * iz; o.y = e.y * iz; o.z = e.z * iz; o.w = e.w * iz;
    ((float4*)(out + (size_t)row * Nn))[tid] = o;
}

// ---------------- mid-step stats: writes P + invZ; epilogue zeros g_rt ----------------
__global__ __launch_bounds__(256) void k_stats() {
    int row = blockIdx.x;
    int tid = threadIdx.x;
    const float4* p = (const float4*)(g_Shat + (size_t)row * Nn);
    float4 v = p[tid];
    float m = fmaxf(fmaxf(v.x, v.y), fmaxf(v.z, v.w));
#pragma unroll
    for (int o = 16; o > 0; o >>= 1) m = fmaxf(m, __shfl_xor_sync(0xffffffffu, m, o));
    __shared__ float sred[8];
    __shared__ float sbc;
    int wid = tid >> 5, lane = tid & 31;
    if (lane == 0) sred[wid] = m;
    __syncthreads();
    if (tid == 0) {
        float mm = sred[0];
#pragma unroll
        for (int i = 1; i < 8; ++i) mm = fmaxf(mm, sred[i]);
        sbc = mm;
    }
    __syncthreads();
    m = sbc;
    float4 e;
    e.x = __expf(v.x - m);
    e.y = __expf(v.y - m);
    e.z = __expf(v.z - m);
    e.w = __expf(v.w - m);
    ((float4*)(g_P + (size_t)row * Nn))[tid] = e;
    float s = e.x + e.y + e.z + e.w;
#pragma unroll
    for (int o = 16; o > 0; o >>= 1) s += __shfl_xor_sync(0xffffffffu, s, o);
    if (lane == 0) sred[wid] = s;
    __syncthreads();
    if (tid == 0) {
        float ss = 0.f;
#pragma unroll
        for (int i = 0; i < 8; ++i) ss += sred[i];
        g_invZ[row] = 1.0f / ss;
    }
    // zero g_rt for next step's k_rt (first 64 blocks cover 16384 float4)
    if (blockIdx.x < 64)
        ((float4*)g_rt)[blockIdx.x * 256 + tid] = make_float4(0.f, 0.f, 0.f, 0.f);
}

// ---------------- final stats: reads Shat, writes normalized S_L directly ----------------
__global__ __launch_bounds__(256) void k_statsF(float* __restrict__ out) {
    int row = blockIdx.x;
    int tid = threadIdx.x;
    const float4* p = (const float4*)(g_Shat + (size_t)row * Nn);
    float4 v = p[tid];
    float m = fmaxf(fmaxf(v.x, v.y), fmaxf(v.z, v.w));
#pragma unroll
    for (int o = 16; o > 0; o >>= 1) m = fmaxf(m, __shfl_xor_sync(0xffffffffu, m, o));
    __shared__ float sred[8];
    __shared__ float sbc;
    int wid = tid >> 5, lane = tid & 31;
    if (lane == 0) sred[wid] = m;
    __syncthreads();
    if (tid == 0) {
        float mm = sred[0];
#pragma unroll
        for (int i = 1; i < 8; ++i) mm = fmaxf(mm, sred[i]);
        sbc = mm;
    }
    __syncthreads();
    m = sbc;
    float4 e;
    e.x = __expf(v.x - m);
    e.y = __expf(v.y - m);
    e.z = __expf(v.z - m);
    e.w = __expf(v.w - m);
    float s = e.x + e.y + e.z + e.w;
#pragma unroll
    for (int o = 16; o > 0; o >>= 1) s += __shfl_xor_sync(0xffffffffu, s, o);
    if (lane == 0) sred[wid] = s;
    __syncthreads();
    if (tid == 0) {
        float ss = 0.f;
#pragma unroll
        for (int i = 0; i < 8; ++i) ss += sred[i];
        sbc = 1.0f / ss;
    }
    __syncthreads();
    float iz = sbc;
    float4 o;
    o.x = e.x * iz; o.y = e.y * iz; o.z = e.z * iz; o.w = e.w * iz;
    ((float4*)(out + (size_t)row * Nn))[tid] = o;
}

// ---------------- r_t = softmax(S_hat)^T @ r_s; prologue zeros g_aggR ----------------
// grid (4 t-chunks, 16 s-chunks, B); 256 threads
__global__ __launch_bounds__(256) void k_rt(const float* __restrict__ rs) {
    __shared__ float s_rs[64][Rr];
    __shared__ float s_iz[64];
    int b = blockIdx.z;
    int t0 = blockIdx.x * 256;
    int s0 = blockIdx.y * 64;
    int tid = threadIdx.x;

    // zero g_aggR for the upcoming scatter16t (aggR unused at this point)
    int gl = (((blockIdx.z * gridDim.y + blockIdx.y) * gridDim.x) + blockIdx.x) * 256 + tid;
    if (gl < 16384) ((float4*)g_aggR)[gl] = make_float4(0.f, 0.f, 0.f, 0.f);

#pragma unroll
    for (int i = 0; i < 4; ++i) {
        int lin = tid + 256 * i;
        int r = lin >> 4, c = lin & 15;
        s_rs[r][c] = rs[((size_t)(b * Nn + s0 + r)) * Rr + c];
    }
    if (tid < 64) s_iz[tid] = g_invZ[b * Nn + s0 + tid];
    __syncthreads();

    int t = t0 + tid;
    float acc[Rr];
#pragma unroll
    for (int r = 0; r < Rr; ++r) acc[r] = 0.f;
    const float* sp = g_P + ((size_t)(b * Nn + s0)) * Nn + t;
#pragma unroll 8
    for (int s = 0; s < 64; ++s) {
        float w = sp[(size_t)s * Nn] * s_iz[s];
#pragma unroll
        for (int r = 0; r < Rr; ++r) acc[r] += w * s_rs[s][r];
    }
    float* rt = g_rt + (size_t)(b * Nn + t) * Rr;
#pragma unroll
    for (int q = 0; q < 4; ++q)
        red_add_f4(&rt[4 * q], make_float4(acc[4 * q], acc[4 * q + 1], acc[4 * q + 2], acc[4 * q + 3]));
}

// ---------------- o_s aggregation for BOTH steps (vector red into aggR2) ----------------
__global__ void k_scatter16s(const float* __restrict__ rsteps, const int* __restrict__ ei) {
    int step = blockIdx.y;
    const float* src = rsteps + (size_t)step * BN * Rr;
    int idx = blockIdx.x * blockDim.x + threadIdx.x;   // < E*4
    int e = idx >> 2;
    int q = idx & 3;
    float4 v = *(const float4*)&src[(size_t)ei[e] * Rr + 4 * q];
    red_add_f4(&g_aggR2[step][(size_t)ei[Ee + e] * Rr + 4 * q], v);
}

// ---------------- o_t aggregation (reads g_rt, vector red into aggR) ----------------
__global__ void k_scatter16t(const int* __restrict__ ei) {
    int idx = blockIdx.x * blockDim.x + threadIdx.x;   // < E*4
    int e = idx >> 2;
    int q = idx & 3;
    float4 v = *(const float4*)&g_rt[(size_t)ei[e] * Rr + 4 * q];
    red_add_f4(&g_aggR[(size_t)ei[Ee + e] * Rr + 4 * q], v);
}

// ---------------- psi2 + Wm1 for o_s, BOTH steps -> A_s[step] (with bm1) ----------------
__global__ __launch_bounds__(256) void k_psi2s(
    const float* __restrict__ rsteps,
    const float* __restrict__ W2s, const float* __restrict__ W2n,
    const float* __restrict__ b2v, const float* __restrict__ Wm1,
    const float* __restrict__ bm1v) {
    __shared__ float sr[16][17], sg[16][17], so[16][17];
    __shared__ float sWs[256], sWn[256], sWm[256];
    int step = blockIdx.y;
    int tid = threadIdx.x;
    int r = tid >> 4, j = tid & 15;
    int row0 = blockIdx.x * 16;
    const float* src = rsteps + (size_t)step * BN * Rr;
    sr[r][j] = src[(size_t)(row0 + r) * Rr + j];
    sg[r][j] = g_aggR2[step][(size_t)(row0 + r) * Rr + j];
    sWs[tid] = W2s[tid];
    sWn[tid] = W2n[tid];
    sWm[tid] = Wm1[tid];
    __syncthreads();
    float acc = b2v[j];
#pragma unroll
    for (int k = 0; k < 16; ++k)
        acc += sr[r][k] * sWs[k * 16 + j] + sg[r][k] * sWn[k * 16 + j];
    so[r][j] = fmaxf(acc, 0.f);
    __syncthreads();
    float a2 = bm1v[j];
#pragma unroll
    for (int k = 0; k < 16; ++k) a2 += so[r][k] * sWm[k * 16 + j];
    g_As[step][(size_t)(row0 + r) * Rr + j] = a2;
}

// ---------------- psi2 + Wm1 for o_t -> B_t (no bm1) ----------------
__global__ __launch_bounds__(256) void k_psi2t(
    const float* __restrict__ W2s, const float* __restrict__ W2n,
    const float* __restrict__ b2v, const float* __restrict__ Wm1) {
    __shared__ float sr[16][17], sg[16][17], so[16][17];
    __shared__ float sWs[256], sWn[256], sWm[256];
    int tid = threadIdx.x;
    int r = tid >> 4, j = tid & 15;
    int row0 = blockIdx.x * 16;
    sr[r][j] = g_rt[(size_t)(row0 + r) * Rr + j];
    sg[r][j] = g_aggR[(size_t)(row0 + r) * Rr + j];
    sWs[tid] = W2s[tid];
    sWn[tid] = W2n[tid];
    sWm[tid] = Wm1[tid];
    __syncthreads();
    float acc = b2v[j];
#pragma unroll
    for (int k = 0; k < 16; ++k)
        acc += sr[r][k] * sWs[k * 16 + j] + sg[r][k] * sWn[k * 16 + j];
    so[r][j] = fmaxf(acc, 0.f);
    __syncthreads();
    float a2 = 0.f;
#pragma unroll
    for (int k = 0; k < 16; ++k) a2 += so[r][k] * sWm[k * 16 + j];
    g_Bt[(size_t)(row0 + r) * Rr + j] = a2;
}

// ---------------- S_hat += sum_k relu(A_s[s,k]-B_t[t,k])*Wm2[k] + bm2 ----------------
__global__ __launch_bounds__(256) void k_upd(int step, const float* __restrict__ Wm2,
                                             const float* __restrict__ bm2v) {
    __shared__ float sA[16][16];
    __shared__ float swm[16];
    int b = blockIdx.z;
    int s0 = blockIdx.y * 16;
    int t0 = blockIdx.x * 256;
    int tid = threadIdx.x;
    sA[tid >> 4][tid & 15] = g_As[step][(size_t)(b * Nn + s0 + (tid >> 4)) * Rr + (tid & 15)];
    if (tid < 16) swm[tid] = Wm2[tid];
    float bb = bm2v[0];
    int t = t0 + tid;
    float Bk[16];
    const float4* bp = (const float4*)&g_Bt[(size_t)(b * Nn + t) * Rr];
    float4 b0 = bp[0], b1 = bp[1], b2 = bp[2], b3 = bp[3];
    Bk[0] = b0.x; Bk[1] = b0.y; Bk[2] = b0.z; Bk[3] = b0.w;
    Bk[4] = b1.x; Bk[5] = b1.y; Bk[6] = b1.z; Bk[7] = b1.w;
    Bk[8] = b2.x; Bk[9] = b2.y; Bk[10] = b2.z; Bk[11] = b2.w;
    Bk[12] = b3.x; Bk[13] = b3.y; Bk[14] = b3.z; Bk[15] = b3.w;
    __syncthreads();
    float* shp = g_Shat + ((size_t)(b * Nn + s0)) * Nn + t;
#pragma unroll
    for (int s = 0; s < 16; ++s) {
        float acc = bb;
#pragma unroll
        for (int k = 0; k < 16; ++k)
            acc += fmaxf(sA[s][k] - Bk[k], 0.f) * swm[k];
        shp[(size_t)s * Nn] += acc;
    }
}

// ---------------- host orchestration ----------------
extern "C" void kernel_launch(void* const* d_in, const int* in_sizes, int n_in,
                              void* d_out, int out_size) {
    const float* x_s   = (const float*)d_in[0];
    const int*   ei_s  = (const int*)d_in[1];
    const float* x_t   = (const float*)d_in[2];
    const int*   ei_t  = (const int*)d_in[3];
    const float* W1s   = (const float*)d_in[4];
    const float* W1n   = (const float*)d_in[5];
    const float* b1    = (const float*)d_in[6];
    const float* W2s   = (const float*)d_in[7];
    const float* W2n   = (const float*)d_in[8];
    const float* b2v   = (const float*)d_in[9];
    const float* Wm1   = (const float*)d_in[10];
    const float* bm1v  = (const float*)d_in[11];
    const float* Wm2   = (const float*)d_in[12];
    const float* bm2v  = (const float*)d_in[13];
    const float* rsteps = (const float*)d_in[14];
    float* out = (float*)d_out;

    // single zero pass: agg1 + rt + aggR + aggR2
    k_zero_all<<<1280, 256>>>();

    // psi1
    k_scatter128<<<dim3(Ee * 32 / 256, 2), 256>>>(x_s, x_t, ei_s, ei_t);
    k_psi1<<<dim3(BN / 64, 2, 2), 256>>>(x_s, x_t, W1s, W1n, b1);

    // S_hat (tensor-core) + fused initial stats/P/S_0
    k_shat<<<dim3(Nn / 128, Nn / 128, Bb), 256>>>();
    k_stats0<<<BN, 256>>>(out);

    // hoisted o_s path for BOTH steps (independent of the consensus loop)
    k_scatter16s<<<dim3(Ee * 4 / 256, NSTEPS), 256>>>(rsteps, ei_s);
    k_psi2s<<<dim3(BN / 16, NSTEPS), 256>>>(rsteps, W2s, W2n, b2v, Wm1, bm1v);

    for (int step = 0; step < NSTEPS; ++step) {
        const float* rs = rsteps + (size_t)step * Bb * Nn * Rr;

        // r_t = softmax^T @ r_s (prologue zeros aggR for scatter16t)
        k_rt<<<dim3(4, 16, Bb), 256>>>(rs);

        // o_t path -> B_t
        k_scatter16t<<<Ee * 4 / 256, 256>>>(ei_t);
        k_psi2t<<<BN / 16, 256>>>(W2s, W2n, b2v, Wm1);

        // S_hat += upd ; then stats (mid: P+invZ and re-zero rt; final: S_L)
        k_upd<<<dim3(4, 64, Bb), 256>>>(step, Wm2, bm2v);
        if (step == NSTEPS - 1)
            k_statsF<<<BN, 256>>>(out + (size_t)Bb * Nn * Nn);
        else
            k_stats<<<BN, 256>>>();
    }
}